// round 3
// baseline (speedup 1.0000x reference)
#include <cuda_runtime.h>

#define NMAX 50000
#define EMAX 800000
#define D    128
#define EPSF 1e-6f

// ------------------------- device scratch (no mallocs allowed) -------------
__device__ float g_m[NMAX * D];        // gated mean features
__device__ float g_v[NMAX * D];        // gated var features
__device__ int   g_count[NMAX];        // in-degree histogram
__device__ int   g_start[NMAX + 1];    // CSR row offsets (by dst)
__device__ int   g_cursor[NMAX];       // placement cursors
__device__ int   g_eperm[EMAX];        // edge ids sorted by dst

// ------------------------- f32x2 helpers (FFMA2 path) ----------------------
__device__ __forceinline__ unsigned long long pack2(float lo, float hi) {
    unsigned long long r;
    asm("mov.b64 %0, {%1, %2};" : "=l"(r) : "f"(lo), "f"(hi));
    return r;
}
__device__ __forceinline__ void unpack2(unsigned long long v, float &lo, float &hi) {
    asm("mov.b64 {%0, %1}, %2;" : "=f"(lo), "=f"(hi) : "l"(v));
}
__device__ __forceinline__ void fma2(unsigned long long &acc,
                                     unsigned long long a,
                                     unsigned long long b) {
    asm("fma.rn.f32x2 %0, %1, %2, %0;" : "+l"(acc) : "l"(a), "l"(b));
}

// ------------------------- CSR build -------------------------------------
__global__ void k_zero_count(int n) {
    int i = blockIdx.x * blockDim.x + threadIdx.x;
    if (i < n) g_count[i] = 0;
}

__global__ void k_hist(const int* __restrict__ dst, int e) {
    int i = blockIdx.x * blockDim.x + threadIdx.x;
    if (i < e) atomicAdd(&g_count[dst[i]], 1);
}

// Single-block chunked exclusive scan of g_count -> g_start / g_cursor.
__global__ void k_scan(int n) {
    __shared__ int s[1024];
    int t = threadIdx.x;
    int chunk = (n + 1023) / 1024;
    int lo = t * chunk;
    int hi = min(lo + chunk, n);
    int sum = 0;
    for (int i = lo; i < hi; i++) sum += g_count[i];
    s[t] = sum;
    __syncthreads();
    // Hillis-Steele inclusive scan over 1024 partials
    for (int off = 1; off < 1024; off <<= 1) {
        int val = (t >= off) ? s[t - off] : 0;
        __syncthreads();
        s[t] += val;
        __syncthreads();
    }
    int run = (t == 0) ? 0 : s[t - 1];
    for (int i = lo; i < hi; i++) {
        g_start[i]  = run;
        g_cursor[i] = run;
        run += g_count[i];
    }
    if (t == 1023) g_start[n] = s[1023];
}

__global__ void k_place(const int* __restrict__ dst, int e) {
    int i = blockIdx.x * blockDim.x + threadIdx.x;
    if (i < e) {
        int p = atomicAdd(&g_cursor[dst[i]], 1);
        g_eperm[p] = i;
    }
}

// ------------------------- dense phase ------------------------------------
// Block = 256 threads = 8 warps. Each warp computes 4 nodes x 128 features.
// Lane L owns features [4L, 4L+3] as two packed f32x2 accumulators per node
// per matrix. W rows streamed via LDG.128 (L1-resident: each block reads
// 128KB of W once, fits in L1 with 32KB smem carveout).
__global__ void __launch_bounds__(256, 2)
k_dense(const float* __restrict__ mean, const float* __restrict__ var,
        const float* __restrict__ Wm,   const float* __restrict__ bm,
        const float* __restrict__ Wv,   const float* __restrict__ bv, int n) {
    __shared__ float s_mean[32 * D];
    __shared__ float s_var[32 * D];

    const int tid  = threadIdx.x;
    const int warp = tid >> 5;
    const int lane = tid & 31;
    const int nb   = blockIdx.x * 32;

    // cooperative load of 32 node rows (mean + var), float4 granularity
    for (int i = tid; i < 32 * (D / 4); i += 256) {
        int nl   = i >> 5;            // local node 0..31
        int col4 = (i & 31) << 2;     // feature column 0,4,...,124
        int node = nb + nl;
        float4 a = make_float4(0.f, 0.f, 0.f, 0.f);
        float4 b = make_float4(0.f, 0.f, 0.f, 0.f);
        if (node < n) {
            a = *(const float4*)(mean + (long)node * D + col4);
            b = *(const float4*)(var  + (long)node * D + col4);
        }
        *(float4*)(s_mean + nl * D + col4) = a;
        *(float4*)(s_var  + nl * D + col4) = b;
    }
    __syncthreads();

    const int base = warp << 2;  // this warp's first local node

    unsigned long long accm[4][2], accv[4][2];
#pragma unroll
    for (int i = 0; i < 4; i++) {
        accm[i][0] = 0ull; accm[i][1] = 0ull;
        accv[i][0] = 0ull; accv[i][1] = 0ull;
    }

    const float4* Wm4 = (const float4*)Wm;
    const float4* Wv4 = (const float4*)Wv;

    for (int k = 0; k < D; k += 4) {
        float4 am[4], av[4];
#pragma unroll
        for (int i = 0; i < 4; i++) {
            am[i] = *(const float4*)(s_mean + (base + i) * D + k);
            av[i] = *(const float4*)(s_var  + (base + i) * D + k);
        }
#pragma unroll
        for (int kk = 0; kk < 4; kk++) {
            float4 wm = __ldg(&Wm4[(k + kk) * (D / 4) + lane]);
            float4 wv = __ldg(&Wv4[(k + kk) * (D / 4) + lane]);
            unsigned long long wm01 = pack2(wm.x, wm.y);
            unsigned long long wm23 = pack2(wm.z, wm.w);
            unsigned long long wv01 = pack2(wv.x, wv.y);
            unsigned long long wv23 = pack2(wv.z, wv.w);
#pragma unroll
            for (int i = 0; i < 4; i++) {
                float a, b;
                if      (kk == 0) { a = am[i].x; b = av[i].x; }
                else if (kk == 1) { a = am[i].y; b = av[i].y; }
                else if (kk == 2) { a = am[i].z; b = av[i].z; }
                else              { a = am[i].w; b = av[i].w; }
                unsigned long long aa = pack2(a, a);
                unsigned long long bb = pack2(b, b);
                fma2(accm[i][0], wm01, aa);
                fma2(accm[i][1], wm23, aa);
                fma2(accv[i][0], wv01, bb);
                fma2(accv[i][1], wv23, bb);
            }
        }
    }

    // epilogue: +bias, ELU / ReLU+eps, attention gate, store
    float4 bm4 = __ldg((const float4*)bm + lane);
    float4 bv4 = __ldg((const float4*)bv + lane);

#pragma unroll
    for (int i = 0; i < 4; i++) {
        int node = nb + base + i;
        if (node >= n) continue;
        float m0, m1, m2, m3, v0, v1, v2, v3;
        unpack2(accm[i][0], m0, m1);
        unpack2(accm[i][1], m2, m3);
        unpack2(accv[i][0], v0, v1);
        unpack2(accv[i][1], v2, v3);
        m0 += bm4.x; m1 += bm4.y; m2 += bm4.z; m3 += bm4.w;
        v0 += bv4.x; v1 += bv4.y; v2 += bv4.z; v3 += bv4.w;
        // elu
        m0 = (m0 > 0.f) ? m0 : expm1f(m0);
        m1 = (m1 > 0.f) ? m1 : expm1f(m1);
        m2 = (m2 > 0.f) ? m2 : expm1f(m2);
        m3 = (m3 > 0.f) ? m3 : expm1f(m3);
        // relu + eps
        v0 = fmaxf(v0, 0.f) + EPSF;
        v1 = fmaxf(v1, 0.f) + EPSF;
        v2 = fmaxf(v2, 0.f) + EPSF;
        v3 = fmaxf(v3, 0.f) + EPSF;
        // gate
        float a0 = __expf(-v0), a1 = __expf(-v1), a2 = __expf(-v2), a3 = __expf(-v3);
        m0 *= a0; m1 *= a1; m2 *= a2; m3 *= a3;
        v0 *= a0 * a0; v1 *= a1 * a1; v2 *= a2 * a2; v3 *= a3 * a3;
        float4 om = make_float4(m0, m1, m2, m3);
        float4 ov = make_float4(v0, v1, v2, v3);
        *(float4*)(g_m + (long)node * D + lane * 4) = om;
        *(float4*)(g_v + (long)node * D + lane * 4) = ov;
    }
}

// ------------------------- aggregation ------------------------------------
// One warp per destination node. Register accumulators, no atomics.
__global__ void __launch_bounds__(256)
k_agg(const int* __restrict__ esrc, const float* __restrict__ w0,
      const float* __restrict__ w1, float* __restrict__ out, int n) {
    int gwarp = (blockIdx.x * blockDim.x + threadIdx.x) >> 5;
    int lane  = threadIdx.x & 31;
    if (gwarp >= n) return;

    int s = g_start[gwarp];
    int t = g_start[gwarp + 1];

    float4 am = make_float4(0.f, 0.f, 0.f, 0.f);
    float4 av = make_float4(0.f, 0.f, 0.f, 0.f);

    const float4* m4 = (const float4*)g_m;
    const float4* v4 = (const float4*)g_v;

#pragma unroll 2
    for (int idx = s; idx < t; idx++) {
        int e   = __ldg(&g_eperm[idx]);
        int src = __ldg(&esrc[e]);
        float a0 = __ldg(&w0[e]);
        float a1 = __ldg(&w1[e]);
        float4 mm = __ldg(&m4[(long)src * 32 + lane]);
        float4 vv = __ldg(&v4[(long)src * 32 + lane]);
        am.x = fmaf(a0, mm.x, am.x);
        am.y = fmaf(a0, mm.y, am.y);
        am.z = fmaf(a0, mm.z, am.z);
        am.w = fmaf(a0, mm.w, am.w);
        av.x = fmaf(a1, vv.x, av.x);
        av.y = fmaf(a1, vv.y, av.y);
        av.z = fmaf(a1, vv.z, av.z);
        av.w = fmaf(a1, vv.w, av.w);
    }

    float4* outm = (float4*)out;
    float4* outv = (float4*)(out + (long)n * D);
    outm[(long)gwarp * 32 + lane] = am;
    outv[(long)gwarp * 32 + lane] = av;
}

// ------------------------- launch -----------------------------------------
extern "C" void kernel_launch(void* const* d_in, const int* in_sizes, int n_in,
                              void* d_out, int out_size) {
    const float* mean = (const float*)d_in[0];
    const float* var  = (const float*)d_in[1];
    const float* Wm   = (const float*)d_in[2];
    const float* bm   = (const float*)d_in[3];
    const float* Wv   = (const float*)d_in[4];
    const float* bv   = (const float*)d_in[5];
    const float* a0   = (const float*)d_in[6];
    const float* a1   = (const float*)d_in[7];
    const int*   esrc = (const int*)d_in[8];
    const int*   edst = (const int*)d_in[9];

    int n = in_sizes[0] / D;   // 50000
    int e = in_sizes[6];       // 800000

    // CSR build (by destination)
    k_zero_count<<<(n + 255) / 256, 256>>>(n);
    k_hist<<<(e + 255) / 256, 256>>>(edst, e);
    k_scan<<<1, 1024>>>(n);
    k_place<<<(e + 255) / 256, 256>>>(edst, e);

    // Dense projections + gating
    k_dense<<<(n + 31) / 32, 256>>>(mean, var, Wm, bm, Wv, bv, n);

    // Gather-based aggregation (one warp per dst node)
    int warps = n;
    int blocks = (warps * 32 + 255) / 256;
    k_agg<<<blocks, 256>>>(esrc, a0, a1, (float*)d_out, n);
}

// round 6
// speedup vs baseline: 1.0007x; 1.0007x over previous
#include <cuda_runtime.h>

#define NMAX 50000
#define EMAX 800000
#define D    128
#define EPSF 1e-6f

// ------------------------- device scratch (no mallocs allowed) -------------
__device__ float g_m[NMAX * D];        // gated mean features
__device__ float g_v[NMAX * D];        // gated var features
__device__ int   g_count[NMAX];        // in-degree histogram
__device__ int   g_start[NMAX + 1];    // CSR row offsets (by dst)
__device__ int   g_cursor[NMAX];       // placement cursors
__device__ int   g_eperm[EMAX];        // edge ids sorted by dst

// ------------------------- f32x2 helpers (FFMA2 path) ----------------------
__device__ __forceinline__ unsigned long long pack2(float lo, float hi) {
    unsigned long long r;
    asm("mov.b64 %0, {%1, %2};" : "=l"(r) : "f"(lo), "f"(hi));
    return r;
}
__device__ __forceinline__ void unpack2(unsigned long long v, float &lo, float &hi) {
    asm("mov.b64 {%0, %1}, %2;" : "=f"(lo), "=f"(hi) : "l"(v));
}
__device__ __forceinline__ void fma2(unsigned long long &acc,
                                     unsigned long long a,
                                     unsigned long long b) {
    asm("fma.rn.f32x2 %0, %1, %2, %0;" : "+l"(acc) : "l"(a), "l"(b));
}

// ------------------------- CSR build -------------------------------------
__global__ void k_zero_count(int n) {
    int i = blockIdx.x * blockDim.x + threadIdx.x;
    if (i < n) g_count[i] = 0;
}

__global__ void k_hist(const int* __restrict__ dst, int e) {
    int i = blockIdx.x * blockDim.x + threadIdx.x;
    if (i < e) atomicAdd(&g_count[dst[i]], 1);
}

// Single-block chunked exclusive scan of g_count -> g_start / g_cursor.
__global__ void k_scan(int n) {
    __shared__ int s[1024];
    int t = threadIdx.x;
    int chunk = (n + 1023) / 1024;
    int lo = t * chunk;
    int hi = min(lo + chunk, n);
    int sum = 0;
    for (int i = lo; i < hi; i++) sum += g_count[i];
    s[t] = sum;
    __syncthreads();
    // Hillis-Steele inclusive scan over 1024 partials
    for (int off = 1; off < 1024; off <<= 1) {
        int val = (t >= off) ? s[t - off] : 0;
        __syncthreads();
        s[t] += val;
        __syncthreads();
    }
    int run = (t == 0) ? 0 : s[t - 1];
    for (int i = lo; i < hi; i++) {
        g_start[i]  = run;
        g_cursor[i] = run;
        run += g_count[i];
    }
    if (t == 1023) g_start[n] = s[1023];
}

__global__ void k_place(const int* __restrict__ dst, int e) {
    int i = blockIdx.x * blockDim.x + threadIdx.x;
    if (i < e) {
        int p = atomicAdd(&g_cursor[dst[i]], 1);
        g_eperm[p] = i;
    }
}

// ------------------------- dense phase ------------------------------------
// Block = 256 threads = 8 warps. Each warp computes 4 nodes x 128 features.
// Lane L owns features [4L, 4L+3] as two packed f32x2 accumulators per node
// per matrix. W rows streamed via LDG.128 (L1-resident: each block reads
// 128KB of W once, fits in L1 with 32KB smem carveout).
__global__ void __launch_bounds__(256, 2)
k_dense(const float* __restrict__ mean, const float* __restrict__ var,
        const float* __restrict__ Wm,   const float* __restrict__ bm,
        const float* __restrict__ Wv,   const float* __restrict__ bv, int n) {
    __shared__ float s_mean[32 * D];
    __shared__ float s_var[32 * D];

    const int tid  = threadIdx.x;
    const int warp = tid >> 5;
    const int lane = tid & 31;
    const int nb   = blockIdx.x * 32;

    // cooperative load of 32 node rows (mean + var), float4 granularity
    for (int i = tid; i < 32 * (D / 4); i += 256) {
        int nl   = i >> 5;            // local node 0..31
        int col4 = (i & 31) << 2;     // feature column 0,4,...,124
        int node = nb + nl;
        float4 a = make_float4(0.f, 0.f, 0.f, 0.f);
        float4 b = make_float4(0.f, 0.f, 0.f, 0.f);
        if (node < n) {
            a = *(const float4*)(mean + (long)node * D + col4);
            b = *(const float4*)(var  + (long)node * D + col4);
        }
        *(float4*)(s_mean + nl * D + col4) = a;
        *(float4*)(s_var  + nl * D + col4) = b;
    }
    __syncthreads();

    const int base = warp << 2;  // this warp's first local node

    unsigned long long accm[4][2], accv[4][2];
#pragma unroll
    for (int i = 0; i < 4; i++) {
        accm[i][0] = 0ull; accm[i][1] = 0ull;
        accv[i][0] = 0ull; accv[i][1] = 0ull;
    }

    const float4* Wm4 = (const float4*)Wm;
    const float4* Wv4 = (const float4*)Wv;

    for (int k = 0; k < D; k += 4) {
        float4 am[4], av[4];
#pragma unroll
        for (int i = 0; i < 4; i++) {
            am[i] = *(const float4*)(s_mean + (base + i) * D + k);
            av[i] = *(const float4*)(s_var  + (base + i) * D + k);
        }
#pragma unroll
        for (int kk = 0; kk < 4; kk++) {
            float4 wm = __ldg(&Wm4[(k + kk) * (D / 4) + lane]);
            float4 wv = __ldg(&Wv4[(k + kk) * (D / 4) + lane]);
            unsigned long long wm01 = pack2(wm.x, wm.y);
            unsigned long long wm23 = pack2(wm.z, wm.w);
            unsigned long long wv01 = pack2(wv.x, wv.y);
            unsigned long long wv23 = pack2(wv.z, wv.w);
#pragma unroll
            for (int i = 0; i < 4; i++) {
                float a, b;
                if      (kk == 0) { a = am[i].x; b = av[i].x; }
                else if (kk == 1) { a = am[i].y; b = av[i].y; }
                else if (kk == 2) { a = am[i].z; b = av[i].z; }
                else              { a = am[i].w; b = av[i].w; }
                unsigned long long aa = pack2(a, a);
                unsigned long long bb = pack2(b, b);
                fma2(accm[i][0], wm01, aa);
                fma2(accm[i][1], wm23, aa);
                fma2(accv[i][0], wv01, bb);
                fma2(accv[i][1], wv23, bb);
            }
        }
    }

    // epilogue: +bias, ELU / ReLU+eps, attention gate, store
    float4 bm4 = __ldg((const float4*)bm + lane);
    float4 bv4 = __ldg((const float4*)bv + lane);

#pragma unroll
    for (int i = 0; i < 4; i++) {
        int node = nb + base + i;
        if (node >= n) continue;
        float m0, m1, m2, m3, v0, v1, v2, v3;
        unpack2(accm[i][0], m0, m1);
        unpack2(accm[i][1], m2, m3);
        unpack2(accv[i][0], v0, v1);
        unpack2(accv[i][1], v2, v3);
        m0 += bm4.x; m1 += bm4.y; m2 += bm4.z; m3 += bm4.w;
        v0 += bv4.x; v1 += bv4.y; v2 += bv4.z; v3 += bv4.w;
        // elu
        m0 = (m0 > 0.f) ? m0 : expm1f(m0);
        m1 = (m1 > 0.f) ? m1 : expm1f(m1);
        m2 = (m2 > 0.f) ? m2 : expm1f(m2);
        m3 = (m3 > 0.f) ? m3 : expm1f(m3);
        // relu + eps
        v0 = fmaxf(v0, 0.f) + EPSF;
        v1 = fmaxf(v1, 0.f) + EPSF;
        v2 = fmaxf(v2, 0.f) + EPSF;
        v3 = fmaxf(v3, 0.f) + EPSF;
        // gate
        float a0 = __expf(-v0), a1 = __expf(-v1), a2 = __expf(-v2), a3 = __expf(-v3);
        m0 *= a0; m1 *= a1; m2 *= a2; m3 *= a3;
        v0 *= a0 * a0; v1 *= a1 * a1; v2 *= a2 * a2; v3 *= a3 * a3;
        float4 om = make_float4(m0, m1, m2, m3);
        float4 ov = make_float4(v0, v1, v2, v3);
        *(float4*)(g_m + (long)node * D + lane * 4) = om;
        *(float4*)(g_v + (long)node * D + lane * 4) = ov;
    }
}

// ------------------------- aggregation ------------------------------------
// One warp per destination node. Register accumulators, no atomics.
__global__ void __launch_bounds__(256)
k_agg(const int* __restrict__ esrc, const float* __restrict__ w0,
      const float* __restrict__ w1, float* __restrict__ out, int n) {
    int gwarp = (blockIdx.x * blockDim.x + threadIdx.x) >> 5;
    int lane  = threadIdx.x & 31;
    if (gwarp >= n) return;

    int s = g_start[gwarp];
    int t = g_start[gwarp + 1];

    float4 am = make_float4(0.f, 0.f, 0.f, 0.f);
    float4 av = make_float4(0.f, 0.f, 0.f, 0.f);

    const float4* m4 = (const float4*)g_m;
    const float4* v4 = (const float4*)g_v;

#pragma unroll 2
    for (int idx = s; idx < t; idx++) {
        int e   = __ldg(&g_eperm[idx]);
        int src = __ldg(&esrc[e]);
        float a0 = __ldg(&w0[e]);
        float a1 = __ldg(&w1[e]);
        float4 mm = __ldg(&m4[(long)src * 32 + lane]);
        float4 vv = __ldg(&v4[(long)src * 32 + lane]);
        am.x = fmaf(a0, mm.x, am.x);
        am.y = fmaf(a0, mm.y, am.y);
        am.z = fmaf(a0, mm.z, am.z);
        am.w = fmaf(a0, mm.w, am.w);
        av.x = fmaf(a1, vv.x, av.x);
        av.y = fmaf(a1, vv.y, av.y);
        av.z = fmaf(a1, vv.z, av.z);
        av.w = fmaf(a1, vv.w, av.w);
    }

    float4* outm = (float4*)out;
    float4* outv = (float4*)(out + (long)n * D);
    outm[(long)gwarp * 32 + lane] = am;
    outv[(long)gwarp * 32 + lane] = av;
}

// ------------------------- launch -----------------------------------------
extern "C" void kernel_launch(void* const* d_in, const int* in_sizes, int n_in,
                              void* d_out, int out_size) {
    const float* mean = (const float*)d_in[0];
    const float* var  = (const float*)d_in[1];
    const float* Wm   = (const float*)d_in[2];
    const float* bm   = (const float*)d_in[3];
    const float* Wv   = (const float*)d_in[4];
    const float* bv   = (const float*)d_in[5];
    const float* a0   = (const float*)d_in[6];
    const float* a1   = (const float*)d_in[7];
    const int*   esrc = (const int*)d_in[8];
    const int*   edst = (const int*)d_in[9];

    int n = in_sizes[0] / D;   // 50000
    int e = in_sizes[6];       // 800000

    // CSR build (by destination)
    k_zero_count<<<(n + 255) / 256, 256>>>(n);
    k_hist<<<(e + 255) / 256, 256>>>(edst, e);
    k_scan<<<1, 1024>>>(n);
    k_place<<<(e + 255) / 256, 256>>>(edst, e);

    // Dense projections + gating
    k_dense<<<(n + 31) / 32, 256>>>(mean, var, Wm, bm, Wv, bv, n);

    // Gather-based aggregation (one warp per dst node)
    int warps = n;
    int blocks = (warps * 32 + 255) / 256;
    k_agg<<<blocks, 256>>>(esrc, a0, a1, (float*)d_out, n);
}

// round 7
// speedup vs baseline: 1.0009x; 1.0002x over previous
#include <cuda_runtime.h>

#define NMAX 50000
#define EMAX 800000
#define D    128
#define EPSF 1e-6f

// ------------------------- device scratch (no mallocs allowed) -------------
__device__ float g_m[NMAX * D];        // gated mean features
__device__ float g_v[NMAX * D];        // gated var features
__device__ int   g_count[NMAX];        // in-degree histogram
__device__ int   g_start[NMAX + 1];    // CSR row offsets (by dst)
__device__ int   g_cursor[NMAX];       // placement cursors
__device__ int   g_eperm[EMAX];        // edge ids sorted by dst

// ------------------------- f32x2 helpers (FFMA2 path) ----------------------
__device__ __forceinline__ unsigned long long pack2(float lo, float hi) {
    unsigned long long r;
    asm("mov.b64 %0, {%1, %2};" : "=l"(r) : "f"(lo), "f"(hi));
    return r;
}
__device__ __forceinline__ void unpack2(unsigned long long v, float &lo, float &hi) {
    asm("mov.b64 {%0, %1}, %2;" : "=f"(lo), "=f"(hi) : "l"(v));
}
__device__ __forceinline__ void fma2(unsigned long long &acc,
                                     unsigned long long a,
                                     unsigned long long b) {
    asm("fma.rn.f32x2 %0, %1, %2, %0;" : "+l"(acc) : "l"(a), "l"(b));
}

// ------------------------- CSR build -------------------------------------
__global__ void k_zero_count(int n) {
    int i = blockIdx.x * blockDim.x + threadIdx.x;
    if (i < n) g_count[i] = 0;
}

__global__ void k_hist(const int* __restrict__ dst, int e) {
    int i = blockIdx.x * blockDim.x + threadIdx.x;
    if (i < e) atomicAdd(&g_count[dst[i]], 1);
}

// Single-block chunked exclusive scan of g_count -> g_start / g_cursor.
__global__ void k_scan(int n) {
    __shared__ int s[1024];
    int t = threadIdx.x;
    int chunk = (n + 1023) / 1024;
    int lo = t * chunk;
    int hi = min(lo + chunk, n);
    int sum = 0;
    for (int i = lo; i < hi; i++) sum += g_count[i];
    s[t] = sum;
    __syncthreads();
    // Hillis-Steele inclusive scan over 1024 partials
    for (int off = 1; off < 1024; off <<= 1) {
        int val = (t >= off) ? s[t - off] : 0;
        __syncthreads();
        s[t] += val;
        __syncthreads();
    }
    int run = (t == 0) ? 0 : s[t - 1];
    for (int i = lo; i < hi; i++) {
        g_start[i]  = run;
        g_cursor[i] = run;
        run += g_count[i];
    }
    if (t == 1023) g_start[n] = s[1023];
}

__global__ void k_place(const int* __restrict__ dst, int e) {
    int i = blockIdx.x * blockDim.x + threadIdx.x;
    if (i < e) {
        int p = atomicAdd(&g_cursor[dst[i]], 1);
        g_eperm[p] = i;
    }
}

// ------------------------- dense phase ------------------------------------
// Block = 256 threads = 8 warps. Each warp computes 4 nodes x 128 features.
// Lane L owns features [4L, 4L+3] as two packed f32x2 accumulators per node
// per matrix. W rows streamed via LDG.128 (L1-resident: each block reads
// 128KB of W once, fits in L1 with 32KB smem carveout).
__global__ void __launch_bounds__(256, 2)
k_dense(const float* __restrict__ mean, const float* __restrict__ var,
        const float* __restrict__ Wm,   const float* __restrict__ bm,
        const float* __restrict__ Wv,   const float* __restrict__ bv, int n) {
    __shared__ float s_mean[32 * D];
    __shared__ float s_var[32 * D];

    const int tid  = threadIdx.x;
    const int warp = tid >> 5;
    const int lane = tid & 31;
    const int nb   = blockIdx.x * 32;

    // cooperative load of 32 node rows (mean + var), float4 granularity
    for (int i = tid; i < 32 * (D / 4); i += 256) {
        int nl   = i >> 5;            // local node 0..31
        int col4 = (i & 31) << 2;     // feature column 0,4,...,124
        int node = nb + nl;
        float4 a = make_float4(0.f, 0.f, 0.f, 0.f);
        float4 b = make_float4(0.f, 0.f, 0.f, 0.f);
        if (node < n) {
            a = *(const float4*)(mean + (long)node * D + col4);
            b = *(const float4*)(var  + (long)node * D + col4);
        }
        *(float4*)(s_mean + nl * D + col4) = a;
        *(float4*)(s_var  + nl * D + col4) = b;
    }
    __syncthreads();

    const int base = warp << 2;  // this warp's first local node

    unsigned long long accm[4][2], accv[4][2];
#pragma unroll
    for (int i = 0; i < 4; i++) {
        accm[i][0] = 0ull; accm[i][1] = 0ull;
        accv[i][0] = 0ull; accv[i][1] = 0ull;
    }

    const float4* Wm4 = (const float4*)Wm;
    const float4* Wv4 = (const float4*)Wv;

    for (int k = 0; k < D; k += 4) {
        float4 am[4], av[4];
#pragma unroll
        for (int i = 0; i < 4; i++) {
            am[i] = *(const float4*)(s_mean + (base + i) * D + k);
            av[i] = *(const float4*)(s_var  + (base + i) * D + k);
        }
#pragma unroll
        for (int kk = 0; kk < 4; kk++) {
            float4 wm = __ldg(&Wm4[(k + kk) * (D / 4) + lane]);
            float4 wv = __ldg(&Wv4[(k + kk) * (D / 4) + lane]);
            unsigned long long wm01 = pack2(wm.x, wm.y);
            unsigned long long wm23 = pack2(wm.z, wm.w);
            unsigned long long wv01 = pack2(wv.x, wv.y);
            unsigned long long wv23 = pack2(wv.z, wv.w);
#pragma unroll
            for (int i = 0; i < 4; i++) {
                float a, b;
                if      (kk == 0) { a = am[i].x; b = av[i].x; }
                else if (kk == 1) { a = am[i].y; b = av[i].y; }
                else if (kk == 2) { a = am[i].z; b = av[i].z; }
                else              { a = am[i].w; b = av[i].w; }
                unsigned long long aa = pack2(a, a);
                unsigned long long bb = pack2(b, b);
                fma2(accm[i][0], wm01, aa);
                fma2(accm[i][1], wm23, aa);
                fma2(accv[i][0], wv01, bb);
                fma2(accv[i][1], wv23, bb);
            }
        }
    }

    // epilogue: +bias, ELU / ReLU+eps, attention gate, store
    float4 bm4 = __ldg((const float4*)bm + lane);
    float4 bv4 = __ldg((const float4*)bv + lane);

#pragma unroll
    for (int i = 0; i < 4; i++) {
        int node = nb + base + i;
        if (node >= n) continue;
        float m0, m1, m2, m3, v0, v1, v2, v3;
        unpack2(accm[i][0], m0, m1);
        unpack2(accm[i][1], m2, m3);
        unpack2(accv[i][0], v0, v1);
        unpack2(accv[i][1], v2, v3);
        m0 += bm4.x; m1 += bm4.y; m2 += bm4.z; m3 += bm4.w;
        v0 += bv4.x; v1 += bv4.y; v2 += bv4.z; v3 += bv4.w;
        // elu
        m0 = (m0 > 0.f) ? m0 : expm1f(m0);
        m1 = (m1 > 0.f) ? m1 : expm1f(m1);
        m2 = (m2 > 0.f) ? m2 : expm1f(m2);
        m3 = (m3 > 0.f) ? m3 : expm1f(m3);
        // relu + eps
        v0 = fmaxf(v0, 0.f) + EPSF;
        v1 = fmaxf(v1, 0.f) + EPSF;
        v2 = fmaxf(v2, 0.f) + EPSF;
        v3 = fmaxf(v3, 0.f) + EPSF;
        // gate
        float a0 = __expf(-v0), a1 = __expf(-v1), a2 = __expf(-v2), a3 = __expf(-v3);
        m0 *= a0; m1 *= a1; m2 *= a2; m3 *= a3;
        v0 *= a0 * a0; v1 *= a1 * a1; v2 *= a2 * a2; v3 *= a3 * a3;
        float4 om = make_float4(m0, m1, m2, m3);
        float4 ov = make_float4(v0, v1, v2, v3);
        *(float4*)(g_m + (long)node * D + lane * 4) = om;
        *(float4*)(g_v + (long)node * D + lane * 4) = ov;
    }
}

// ------------------------- aggregation ------------------------------------
// One warp per destination node. Register accumulators, no atomics.
__global__ void __launch_bounds__(256)
k_agg(const int* __restrict__ esrc, const float* __restrict__ w0,
      const float* __restrict__ w1, float* __restrict__ out, int n) {
    int gwarp = (blockIdx.x * blockDim.x + threadIdx.x) >> 5;
    int lane  = threadIdx.x & 31;
    if (gwarp >= n) return;

    int s = g_start[gwarp];
    int t = g_start[gwarp + 1];

    float4 am = make_float4(0.f, 0.f, 0.f, 0.f);
    float4 av = make_float4(0.f, 0.f, 0.f, 0.f);

    const float4* m4 = (const float4*)g_m;
    const float4* v4 = (const float4*)g_v;

#pragma unroll 2
    for (int idx = s; idx < t; idx++) {
        int e   = __ldg(&g_eperm[idx]);
        int src = __ldg(&esrc[e]);
        float a0 = __ldg(&w0[e]);
        float a1 = __ldg(&w1[e]);
        float4 mm = __ldg(&m4[(long)src * 32 + lane]);
        float4 vv = __ldg(&v4[(long)src * 32 + lane]);
        am.x = fmaf(a0, mm.x, am.x);
        am.y = fmaf(a0, mm.y, am.y);
        am.z = fmaf(a0, mm.z, am.z);
        am.w = fmaf(a0, mm.w, am.w);
        av.x = fmaf(a1, vv.x, av.x);
        av.y = fmaf(a1, vv.y, av.y);
        av.z = fmaf(a1, vv.z, av.z);
        av.w = fmaf(a1, vv.w, av.w);
    }

    float4* outm = (float4*)out;
    float4* outv = (float4*)(out + (long)n * D);
    outm[(long)gwarp * 32 + lane] = am;
    outv[(long)gwarp * 32 + lane] = av;
}

// ------------------------- launch -----------------------------------------
extern "C" void kernel_launch(void* const* d_in, const int* in_sizes, int n_in,
                              void* d_out, int out_size) {
    const float* mean = (const float*)d_in[0];
    const float* var  = (const float*)d_in[1];
    const float* Wm   = (const float*)d_in[2];
    const float* bm   = (const float*)d_in[3];
    const float* Wv   = (const float*)d_in[4];
    const float* bv   = (const float*)d_in[5];
    const float* a0   = (const float*)d_in[6];
    const float* a1   = (const float*)d_in[7];
    const int*   esrc = (const int*)d_in[8];
    const int*   edst = (const int*)d_in[9];

    int n = in_sizes[0] / D;   // 50000
    int e = in_sizes[6];       // 800000

    // CSR build (by destination)
    k_zero_count<<<(n + 255) / 256, 256>>>(n);
    k_hist<<<(e + 255) / 256, 256>>>(edst, e);
    k_scan<<<1, 1024>>>(n);
    k_place<<<(e + 255) / 256, 256>>>(edst, e);

    // Dense projections + gating
    k_dense<<<(n + 31) / 32, 256>>>(mean, var, Wm, bm, Wv, bv, n);

    // Gather-based aggregation (one warp per dst node)
    int warps = n;
    int blocks = (warps * 32 + 255) / 256;
    k_agg<<<blocks, 256>>>(esrc, a0, a1, (float*)d_out, n);
}

// round 11
// speedup vs baseline: 1.4312x; 1.4299x over previous
#include <cuda_runtime.h>
#include <cuda_fp16.h>

#define NMAX 50000
#define EMAX 800000
#define D    128
#define EPSF 1e-6f

// ------------------------- device scratch (no mallocs allowed) -------------
// Interleaved fp16 feature rows: per node 256 halfs = [m0..m127 | v0..v127] (512B)
__device__ uint4 g_h4[NMAX * 32];      // 25.6 MB, 16B-aligned by type
__device__ int   g_count[NMAX];        // in-degree histogram
__device__ int   g_start[NMAX + 1];    // CSR row offsets (by dst)
__device__ int   g_cursor[NMAX];       // placement cursors
__device__ int   g_part[256];          // scan block partials

struct __align__(16) EData { int src; float w0; float w1; int pad; };
__device__ EData g_edata[EMAX];        // dst-sorted edge payload, 12.8 MB

// ------------------------- f32x2 helpers (FFMA2 path) ----------------------
__device__ __forceinline__ unsigned long long pack2(float lo, float hi) {
    unsigned long long r;
    asm("mov.b64 %0, {%1, %2};" : "=l"(r) : "f"(lo), "f"(hi));
    return r;
}
__device__ __forceinline__ void unpack2(unsigned long long v, float &lo, float &hi) {
    asm("mov.b64 {%0, %1}, %2;" : "=f"(lo), "=f"(hi) : "l"(v));
}
__device__ __forceinline__ void fma2(unsigned long long &acc,
                                     unsigned long long a,
                                     unsigned long long b) {
    asm("fma.rn.f32x2 %0, %1, %2, %0;" : "+l"(acc) : "l"(a), "l"(b));
}

// ------------------------- CSR build -------------------------------------
__global__ void k_zero_count(int n) {
    int i = blockIdx.x * blockDim.x + threadIdx.x;
    if (i < n) g_count[i] = 0;
}

__global__ void k_hist(const int* __restrict__ dst, int e) {
    int i = blockIdx.x * blockDim.x + threadIdx.x;
    if (i < e) atomicAdd(&g_count[dst[i]], 1);
}

// Parallel scan, phase A: per-block sums of g_count.
__global__ void k_scanA(int n) {
    __shared__ int s[256];
    int i = blockIdx.x * 256 + threadIdx.x;
    s[threadIdx.x] = (i < n) ? g_count[i] : 0;
    __syncthreads();
#pragma unroll
    for (int o = 128; o > 0; o >>= 1) {
        if (threadIdx.x < o) s[threadIdx.x] += s[threadIdx.x + o];
        __syncthreads();
    }
    if (threadIdx.x == 0) g_part[blockIdx.x] = s[0];
}

// Phase B: exclusive scan of the (<=256) block partials, single block.
__global__ void k_scanB(int nb) {
    __shared__ int s[256];
    int t = threadIdx.x;
    s[t] = (t < nb) ? g_part[t] : 0;
    __syncthreads();
#pragma unroll
    for (int o = 1; o < 256; o <<= 1) {
        int v = (t >= o) ? s[t - o] : 0;
        __syncthreads();
        s[t] += v;
        __syncthreads();
    }
    if (t < nb) g_part[t] = (t == 0) ? 0 : s[t - 1];
}

// Phase C: local exclusive scan + block offset -> g_start/g_cursor.
__global__ void k_scanC(int n) {
    __shared__ int s[256];
    int i = blockIdx.x * 256 + threadIdx.x;
    int c = (i < n) ? g_count[i] : 0;
    s[threadIdx.x] = c;
    __syncthreads();
#pragma unroll
    for (int o = 1; o < 256; o <<= 1) {
        int v = (threadIdx.x >= o) ? s[threadIdx.x - o] : 0;
        __syncthreads();
        s[threadIdx.x] += v;
        __syncthreads();
    }
    int ex = s[threadIdx.x] - c + g_part[blockIdx.x];
    if (i < n) {
        g_start[i]  = ex;
        g_cursor[i] = ex;
        if (i == n - 1) g_start[n] = ex + c;
    }
}

// Placement: scatter full 16B edge payload {src, w0, w1} into sorted slot.
__global__ void k_place(const int* __restrict__ dst, const int* __restrict__ esrc,
                        const float* __restrict__ w0, const float* __restrict__ w1,
                        int e) {
    int i = blockIdx.x * blockDim.x + threadIdx.x;
    if (i < e) {
        int p = atomicAdd(&g_cursor[dst[i]], 1);
        EData ed;
        ed.src = esrc[i];
        ed.w0  = w0[i];
        ed.w1  = w1[i];
        ed.pad = 0;
        *(uint4*)&g_edata[p] = *(uint4*)&ed;
    }
}

// ------------------------- dense phase ------------------------------------
// Block = 256 threads = 8 warps. Each warp computes 4 nodes x 128 features.
// Lane L owns features [4L, 4L+3]; fp32 FFMA2 accumulation, fp16 store.
__global__ void __launch_bounds__(256, 2)
k_dense(const float* __restrict__ mean, const float* __restrict__ var,
        const float* __restrict__ Wm,   const float* __restrict__ bm,
        const float* __restrict__ Wv,   const float* __restrict__ bv, int n) {
    __shared__ float s_mean[32 * D];
    __shared__ float s_var[32 * D];

    const int tid  = threadIdx.x;
    const int warp = tid >> 5;
    const int lane = tid & 31;
    const int nb   = blockIdx.x * 32;

    for (int i = tid; i < 32 * (D / 4); i += 256) {
        int nl   = i >> 5;
        int col4 = (i & 31) << 2;
        int node = nb + nl;
        float4 a = make_float4(0.f, 0.f, 0.f, 0.f);
        float4 b = make_float4(0.f, 0.f, 0.f, 0.f);
        if (node < n) {
            a = *(const float4*)(mean + (long)node * D + col4);
            b = *(const float4*)(var  + (long)node * D + col4);
        }
        *(float4*)(s_mean + nl * D + col4) = a;
        *(float4*)(s_var  + nl * D + col4) = b;
    }
    __syncthreads();

    const int base = warp << 2;

    unsigned long long accm[4][2], accv[4][2];
#pragma unroll
    for (int i = 0; i < 4; i++) {
        accm[i][0] = 0ull; accm[i][1] = 0ull;
        accv[i][0] = 0ull; accv[i][1] = 0ull;
    }

    const float4* Wm4 = (const float4*)Wm;
    const float4* Wv4 = (const float4*)Wv;

    for (int k = 0; k < D; k += 4) {
        float4 am[4], av[4];
#pragma unroll
        for (int i = 0; i < 4; i++) {
            am[i] = *(const float4*)(s_mean + (base + i) * D + k);
            av[i] = *(const float4*)(s_var  + (base + i) * D + k);
        }
#pragma unroll
        for (int kk = 0; kk < 4; kk++) {
            float4 wm = __ldg(&Wm4[(k + kk) * (D / 4) + lane]);
            float4 wv = __ldg(&Wv4[(k + kk) * (D / 4) + lane]);
            unsigned long long wm01 = pack2(wm.x, wm.y);
            unsigned long long wm23 = pack2(wm.z, wm.w);
            unsigned long long wv01 = pack2(wv.x, wv.y);
            unsigned long long wv23 = pack2(wv.z, wv.w);
#pragma unroll
            for (int i = 0; i < 4; i++) {
                float a, b;
                if      (kk == 0) { a = am[i].x; b = av[i].x; }
                else if (kk == 1) { a = am[i].y; b = av[i].y; }
                else if (kk == 2) { a = am[i].z; b = av[i].z; }
                else              { a = am[i].w; b = av[i].w; }
                unsigned long long aa = pack2(a, a);
                unsigned long long bb = pack2(b, b);
                fma2(accm[i][0], wm01, aa);
                fma2(accm[i][1], wm23, aa);
                fma2(accv[i][0], wv01, bb);
                fma2(accv[i][1], wv23, bb);
            }
        }
    }

    float4 bm4 = __ldg((const float4*)bm + lane);
    float4 bv4 = __ldg((const float4*)bv + lane);

#pragma unroll
    for (int i = 0; i < 4; i++) {
        int node = nb + base + i;
        if (node >= n) continue;
        float m0, m1, m2, m3, v0, v1, v2, v3;
        unpack2(accm[i][0], m0, m1);
        unpack2(accm[i][1], m2, m3);
        unpack2(accv[i][0], v0, v1);
        unpack2(accv[i][1], v2, v3);
        m0 += bm4.x; m1 += bm4.y; m2 += bm4.z; m3 += bm4.w;
        v0 += bv4.x; v1 += bv4.y; v2 += bv4.z; v3 += bv4.w;
        m0 = (m0 > 0.f) ? m0 : expm1f(m0);
        m1 = (m1 > 0.f) ? m1 : expm1f(m1);
        m2 = (m2 > 0.f) ? m2 : expm1f(m2);
        m3 = (m3 > 0.f) ? m3 : expm1f(m3);
        v0 = fmaxf(v0, 0.f) + EPSF;
        v1 = fmaxf(v1, 0.f) + EPSF;
        v2 = fmaxf(v2, 0.f) + EPSF;
        v3 = fmaxf(v3, 0.f) + EPSF;
        float a0 = __expf(-v0), a1 = __expf(-v1), a2 = __expf(-v2), a3 = __expf(-v3);
        m0 *= a0; m1 *= a1; m2 *= a2; m3 *= a3;
        v0 *= a0 * a0; v1 *= a1 * a1; v2 *= a2 * a2; v3 *= a3 * a3;

        // fp16 pack + 8B stores into the interleaved row
        __half* row = (__half*)g_h4 + (long)node * 256;
        __half2 hm01 = __floats2half2_rn(m0, m1);
        __half2 hm23 = __floats2half2_rn(m2, m3);
        __half2 hv01 = __floats2half2_rn(v0, v1);
        __half2 hv23 = __floats2half2_rn(v2, v3);
        uint2 um, uv;
        um.x = reinterpret_cast<unsigned&>(hm01);
        um.y = reinterpret_cast<unsigned&>(hm23);
        uv.x = reinterpret_cast<unsigned&>(hv01);
        uv.y = reinterpret_cast<unsigned&>(hv23);
        *(uint2*)(row + 4 * lane)       = um;   // m features 4L..4L+3
        *(uint2*)(row + 128 + 4 * lane) = uv;   // v features 4L..4L+3
    }
}

// ------------------------- aggregation ------------------------------------
// One warp per dst node. Lanes 0-15 own m features (8 each), lanes 16-31 own
// v features. Per edge: one uniform 16B payload load + one 16B fp16 gather
// per lane (512B/warp). fp32 accumulate via FFMA2, no atomics.
__global__ void __launch_bounds__(256)
k_agg(float* __restrict__ out, int n) {
    int gwarp = (blockIdx.x * blockDim.x + threadIdx.x) >> 5;
    int lane  = threadIdx.x & 31;
    if (gwarp >= n) return;

    int s = g_start[gwarp];
    int t = g_start[gwarp + 1];

    const bool isv = lane >= 16;
    const int  l16 = lane & 15;
    const int  fo  = l16 * 8 + (isv ? 128 : 0);   // half offset within row

    unsigned long long acc0 = 0ull, acc1 = 0ull, acc2 = 0ull, acc3 = 0ull;

    if (s < t) {
        EData ed = g_edata[s];   // uniform broadcast load
        for (int idx = s; idx < t; idx++) {
            EData cur = ed;
            if (idx + 1 < t) ed = g_edata[idx + 1];   // prefetch next payload
            float w = isv ? cur.w1 : cur.w0;
            unsigned long long ww = pack2(w, w);
            uint4 hv = *(const uint4*)((const __half*)g_h4 + (long)cur.src * 256 + fo);
            __half2 h0 = reinterpret_cast<__half2&>(hv.x);
            __half2 h1 = reinterpret_cast<__half2&>(hv.y);
            __half2 h2 = reinterpret_cast<__half2&>(hv.z);
            __half2 h3 = reinterpret_cast<__half2&>(hv.w);
            float2 f0 = __half22float2(h0);
            float2 f1 = __half22float2(h1);
            float2 f2 = __half22float2(h2);
            float2 f3 = __half22float2(h3);
            fma2(acc0, pack2(f0.x, f0.y), ww);
            fma2(acc1, pack2(f1.x, f1.y), ww);
            fma2(acc2, pack2(f2.x, f2.y), ww);
            fma2(acc3, pack2(f3.x, f3.y), ww);
        }
    }

    float r0, r1, r2, r3, r4, r5, r6, r7;
    unpack2(acc0, r0, r1);
    unpack2(acc1, r2, r3);
    unpack2(acc2, r4, r5);
    unpack2(acc3, r6, r7);

    long rowbase = isv ? ((long)n * D + (long)gwarp * D) : ((long)gwarp * D);
    float* o = out + rowbase + l16 * 8;
    *(float4*)(o)     = make_float4(r0, r1, r2, r3);
    *(float4*)(o + 4) = make_float4(r4, r5, r6, r7);
}

// ------------------------- launch -----------------------------------------
extern "C" void kernel_launch(void* const* d_in, const int* in_sizes, int n_in,
                              void* d_out, int out_size) {
    const float* mean = (const float*)d_in[0];
    const float* var  = (const float*)d_in[1];
    const float* Wm   = (const float*)d_in[2];
    const float* bm   = (const float*)d_in[3];
    const float* Wv   = (const float*)d_in[4];
    const float* bv   = (const float*)d_in[5];
    const float* a0   = (const float*)d_in[6];
    const float* a1   = (const float*)d_in[7];
    const int*   esrc = (const int*)d_in[8];
    const int*   edst = (const int*)d_in[9];

    int n = in_sizes[0] / D;   // 50000
    int e = in_sizes[6];       // 800000

    int nb = (n + 255) / 256;  // scan blocks (196 <= 256)

    // CSR build (by destination)
    k_zero_count<<<nb, 256>>>(n);
    k_hist<<<(e + 255) / 256, 256>>>(edst, e);
    k_scanA<<<nb, 256>>>(n);
    k_scanB<<<1, 256>>>(nb);
    k_scanC<<<nb, 256>>>(n);
    k_place<<<(e + 255) / 256, 256>>>(edst, esrc, a0, a1, e);

    // Dense projections + gating (fp32 compute, fp16 store)
    k_dense<<<(n + 31) / 32, 256>>>(mean, var, Wm, bm, Wv, bv, n);

    // Gather-based aggregation (one warp per dst node)
    int blocks = (n * 32 + 255) / 256;
    k_agg<<<blocks, 256>>>((float*)d_out, n);
}

// round 12
// speedup vs baseline: 1.4347x; 1.0025x over previous
#include <cuda_runtime.h>
#include <cuda_fp16.h>

#define NMAX 50000
#define EMAX 800000
#define D    128
#define EPSF 1e-6f

// ------------------------- device scratch (no mallocs allowed) -------------
// Interleaved fp16 feature rows: per node 256 halfs = [m0..m127 | v0..v127] (512B)
__device__ uint4 g_h4[NMAX * 32];      // 25.6 MB, 16B-aligned by type
__device__ int   g_count[NMAX];        // in-degree histogram
__device__ int   g_start[NMAX + 1];    // CSR row offsets (by dst)
__device__ int   g_cursor[NMAX];       // placement cursors
__device__ int   g_part[256];          // scan block partials

struct __align__(16) EData { int src; float w0; float w1; int pad; };
__device__ EData g_edata[EMAX];        // dst-sorted edge payload, 12.8 MB

// ------------------------- f32x2 helpers (FFMA2 path) ----------------------
__device__ __forceinline__ unsigned long long pack2(float lo, float hi) {
    unsigned long long r;
    asm("mov.b64 %0, {%1, %2};" : "=l"(r) : "f"(lo), "f"(hi));
    return r;
}
__device__ __forceinline__ void unpack2(unsigned long long v, float &lo, float &hi) {
    asm("mov.b64 {%0, %1}, %2;" : "=f"(lo), "=f"(hi) : "l"(v));
}
__device__ __forceinline__ void fma2(unsigned long long &acc,
                                     unsigned long long a,
                                     unsigned long long b) {
    asm("fma.rn.f32x2 %0, %1, %2, %0;" : "+l"(acc) : "l"(a), "l"(b));
}

// ------------------------- CSR build -------------------------------------
__global__ void k_zero_count(int n) {
    int i = blockIdx.x * blockDim.x + threadIdx.x;
    if (i < n) g_count[i] = 0;
}

__global__ void k_hist(const int* __restrict__ dst, int e) {
    int i = blockIdx.x * blockDim.x + threadIdx.x;
    if (i < e) atomicAdd(&g_count[dst[i]], 1);
}

// Parallel scan, phase A: per-block sums of g_count.
__global__ void k_scanA(int n) {
    __shared__ int s[256];
    int i = blockIdx.x * 256 + threadIdx.x;
    s[threadIdx.x] = (i < n) ? g_count[i] : 0;
    __syncthreads();
#pragma unroll
    for (int o = 128; o > 0; o >>= 1) {
        if (threadIdx.x < o) s[threadIdx.x] += s[threadIdx.x + o];
        __syncthreads();
    }
    if (threadIdx.x == 0) g_part[blockIdx.x] = s[0];
}

// Phase B: exclusive scan of the (<=256) block partials, single block.
__global__ void k_scanB(int nb) {
    __shared__ int s[256];
    int t = threadIdx.x;
    s[t] = (t < nb) ? g_part[t] : 0;
    __syncthreads();
#pragma unroll
    for (int o = 1; o < 256; o <<= 1) {
        int v = (t >= o) ? s[t - o] : 0;
        __syncthreads();
        s[t] += v;
        __syncthreads();
    }
    if (t < nb) g_part[t] = (t == 0) ? 0 : s[t - 1];
}

// Phase C: local exclusive scan + block offset -> g_start/g_cursor.
__global__ void k_scanC(int n) {
    __shared__ int s[256];
    int i = blockIdx.x * 256 + threadIdx.x;
    int c = (i < n) ? g_count[i] : 0;
    s[threadIdx.x] = c;
    __syncthreads();
#pragma unroll
    for (int o = 1; o < 256; o <<= 1) {
        int v = (threadIdx.x >= o) ? s[threadIdx.x - o] : 0;
        __syncthreads();
        s[threadIdx.x] += v;
        __syncthreads();
    }
    int ex = s[threadIdx.x] - c + g_part[blockIdx.x];
    if (i < n) {
        g_start[i]  = ex;
        g_cursor[i] = ex;
        if (i == n - 1) g_start[n] = ex + c;
    }
}

// Placement: scatter full 16B edge payload {src, w0, w1} into sorted slot.
__global__ void k_place(const int* __restrict__ dst, const int* __restrict__ esrc,
                        const float* __restrict__ w0, const float* __restrict__ w1,
                        int e) {
    int i = blockIdx.x * blockDim.x + threadIdx.x;
    if (i < e) {
        int p = atomicAdd(&g_cursor[dst[i]], 1);
        EData ed;
        ed.src = esrc[i];
        ed.w0  = w0[i];
        ed.w1  = w1[i];
        ed.pad = 0;
        *(uint4*)&g_edata[p] = *(uint4*)&ed;
    }
}

// ------------------------- dense phase ------------------------------------
// Block = 256 threads = 8 warps. Each warp computes 4 nodes x 128 features.
// Lane L owns features [4L, 4L+3]; fp32 FFMA2 accumulation, fp16 store.
__global__ void __launch_bounds__(256, 2)
k_dense(const float* __restrict__ mean, const float* __restrict__ var,
        const float* __restrict__ Wm,   const float* __restrict__ bm,
        const float* __restrict__ Wv,   const float* __restrict__ bv, int n) {
    __shared__ float s_mean[32 * D];
    __shared__ float s_var[32 * D];

    const int tid  = threadIdx.x;
    const int warp = tid >> 5;
    const int lane = tid & 31;
    const int nb   = blockIdx.x * 32;

    for (int i = tid; i < 32 * (D / 4); i += 256) {
        int nl   = i >> 5;
        int col4 = (i & 31) << 2;
        int node = nb + nl;
        float4 a = make_float4(0.f, 0.f, 0.f, 0.f);
        float4 b = make_float4(0.f, 0.f, 0.f, 0.f);
        if (node < n) {
            a = *(const float4*)(mean + (long)node * D + col4);
            b = *(const float4*)(var  + (long)node * D + col4);
        }
        *(float4*)(s_mean + nl * D + col4) = a;
        *(float4*)(s_var  + nl * D + col4) = b;
    }
    __syncthreads();

    const int base = warp << 2;

    unsigned long long accm[4][2], accv[4][2];
#pragma unroll
    for (int i = 0; i < 4; i++) {
        accm[i][0] = 0ull; accm[i][1] = 0ull;
        accv[i][0] = 0ull; accv[i][1] = 0ull;
    }

    const float4* Wm4 = (const float4*)Wm;
    const float4* Wv4 = (const float4*)Wv;

    for (int k = 0; k < D; k += 4) {
        float4 am[4], av[4];
#pragma unroll
        for (int i = 0; i < 4; i++) {
            am[i] = *(const float4*)(s_mean + (base + i) * D + k);
            av[i] = *(const float4*)(s_var  + (base + i) * D + k);
        }
#pragma unroll
        for (int kk = 0; kk < 4; kk++) {
            float4 wm = __ldg(&Wm4[(k + kk) * (D / 4) + lane]);
            float4 wv = __ldg(&Wv4[(k + kk) * (D / 4) + lane]);
            unsigned long long wm01 = pack2(wm.x, wm.y);
            unsigned long long wm23 = pack2(wm.z, wm.w);
            unsigned long long wv01 = pack2(wv.x, wv.y);
            unsigned long long wv23 = pack2(wv.z, wv.w);
#pragma unroll
            for (int i = 0; i < 4; i++) {
                float a, b;
                if      (kk == 0) { a = am[i].x; b = av[i].x; }
                else if (kk == 1) { a = am[i].y; b = av[i].y; }
                else if (kk == 2) { a = am[i].z; b = av[i].z; }
                else              { a = am[i].w; b = av[i].w; }
                unsigned long long aa = pack2(a, a);
                unsigned long long bb = pack2(b, b);
                fma2(accm[i][0], wm01, aa);
                fma2(accm[i][1], wm23, aa);
                fma2(accv[i][0], wv01, bb);
                fma2(accv[i][1], wv23, bb);
            }
        }
    }

    float4 bm4 = __ldg((const float4*)bm + lane);
    float4 bv4 = __ldg((const float4*)bv + lane);

#pragma unroll
    for (int i = 0; i < 4; i++) {
        int node = nb + base + i;
        if (node >= n) continue;
        float m0, m1, m2, m3, v0, v1, v2, v3;
        unpack2(accm[i][0], m0, m1);
        unpack2(accm[i][1], m2, m3);
        unpack2(accv[i][0], v0, v1);
        unpack2(accv[i][1], v2, v3);
        m0 += bm4.x; m1 += bm4.y; m2 += bm4.z; m3 += bm4.w;
        v0 += bv4.x; v1 += bv4.y; v2 += bv4.z; v3 += bv4.w;
        m0 = (m0 > 0.f) ? m0 : expm1f(m0);
        m1 = (m1 > 0.f) ? m1 : expm1f(m1);
        m2 = (m2 > 0.f) ? m2 : expm1f(m2);
        m3 = (m3 > 0.f) ? m3 : expm1f(m3);
        v0 = fmaxf(v0, 0.f) + EPSF;
        v1 = fmaxf(v1, 0.f) + EPSF;
        v2 = fmaxf(v2, 0.f) + EPSF;
        v3 = fmaxf(v3, 0.f) + EPSF;
        float a0 = __expf(-v0), a1 = __expf(-v1), a2 = __expf(-v2), a3 = __expf(-v3);
        m0 *= a0; m1 *= a1; m2 *= a2; m3 *= a3;
        v0 *= a0 * a0; v1 *= a1 * a1; v2 *= a2 * a2; v3 *= a3 * a3;

        // fp16 pack + 8B stores into the interleaved row
        __half* row = (__half*)g_h4 + (long)node * 256;
        __half2 hm01 = __floats2half2_rn(m0, m1);
        __half2 hm23 = __floats2half2_rn(m2, m3);
        __half2 hv01 = __floats2half2_rn(v0, v1);
        __half2 hv23 = __floats2half2_rn(v2, v3);
        uint2 um, uv;
        um.x = reinterpret_cast<unsigned&>(hm01);
        um.y = reinterpret_cast<unsigned&>(hm23);
        uv.x = reinterpret_cast<unsigned&>(hv01);
        uv.y = reinterpret_cast<unsigned&>(hv23);
        *(uint2*)(row + 4 * lane)       = um;   // m features 4L..4L+3
        *(uint2*)(row + 128 + 4 * lane) = uv;   // v features 4L..4L+3
    }
}

// ------------------------- aggregation ------------------------------------
// One warp per dst node. Lanes 0-15 own m features (8 each), lanes 16-31 own
// v features. Per edge: one uniform 16B payload load + one 16B fp16 gather
// per lane (512B/warp). fp32 accumulate via FFMA2, no atomics.
__global__ void __launch_bounds__(256)
k_agg(float* __restrict__ out, int n) {
    int gwarp = (blockIdx.x * blockDim.x + threadIdx.x) >> 5;
    int lane  = threadIdx.x & 31;
    if (gwarp >= n) return;

    int s = g_start[gwarp];
    int t = g_start[gwarp + 1];

    const bool isv = lane >= 16;
    const int  l16 = lane & 15;
    const int  fo  = l16 * 8 + (isv ? 128 : 0);   // half offset within row

    unsigned long long acc0 = 0ull, acc1 = 0ull, acc2 = 0ull, acc3 = 0ull;

    if (s < t) {
        EData ed = g_edata[s];   // uniform broadcast load
        for (int idx = s; idx < t; idx++) {
            EData cur = ed;
            if (idx + 1 < t) ed = g_edata[idx + 1];   // prefetch next payload
            float w = isv ? cur.w1 : cur.w0;
            unsigned long long ww = pack2(w, w);
            uint4 hv = *(const uint4*)((const __half*)g_h4 + (long)cur.src * 256 + fo);
            __half2 h0 = reinterpret_cast<__half2&>(hv.x);
            __half2 h1 = reinterpret_cast<__half2&>(hv.y);
            __half2 h2 = reinterpret_cast<__half2&>(hv.z);
            __half2 h3 = reinterpret_cast<__half2&>(hv.w);
            float2 f0 = __half22float2(h0);
            float2 f1 = __half22float2(h1);
            float2 f2 = __half22float2(h2);
            float2 f3 = __half22float2(h3);
            fma2(acc0, pack2(f0.x, f0.y), ww);
            fma2(acc1, pack2(f1.x, f1.y), ww);
            fma2(acc2, pack2(f2.x, f2.y), ww);
            fma2(acc3, pack2(f3.x, f3.y), ww);
        }
    }

    float r0, r1, r2, r3, r4, r5, r6, r7;
    unpack2(acc0, r0, r1);
    unpack2(acc1, r2, r3);
    unpack2(acc2, r4, r5);
    unpack2(acc3, r6, r7);

    long rowbase = isv ? ((long)n * D + (long)gwarp * D) : ((long)gwarp * D);
    float* o = out + rowbase + l16 * 8;
    *(float4*)(o)     = make_float4(r0, r1, r2, r3);
    *(float4*)(o + 4) = make_float4(r4, r5, r6, r7);
}

// ------------------------- launch -----------------------------------------
extern "C" void kernel_launch(void* const* d_in, const int* in_sizes, int n_in,
                              void* d_out, int out_size) {
    const float* mean = (const float*)d_in[0];
    const float* var  = (const float*)d_in[1];
    const float* Wm   = (const float*)d_in[2];
    const float* bm   = (const float*)d_in[3];
    const float* Wv   = (const float*)d_in[4];
    const float* bv   = (const float*)d_in[5];
    const float* a0   = (const float*)d_in[6];
    const float* a1   = (const float*)d_in[7];
    const int*   esrc = (const int*)d_in[8];
    const int*   edst = (const int*)d_in[9];

    int n = in_sizes[0] / D;   // 50000
    int e = in_sizes[6];       // 800000

    int nb = (n + 255) / 256;  // scan blocks (196 <= 256)

    // CSR build (by destination)
    k_zero_count<<<nb, 256>>>(n);
    k_hist<<<(e + 255) / 256, 256>>>(edst, e);
    k_scanA<<<nb, 256>>>(n);
    k_scanB<<<1, 256>>>(nb);
    k_scanC<<<nb, 256>>>(n);
    k_place<<<(e + 255) / 256, 256>>>(edst, esrc, a0, a1, e);

    // Dense projections + gating (fp32 compute, fp16 store)
    k_dense<<<(n + 31) / 32, 256>>>(mean, var, Wm, bm, Wv, bv, n);

    // Gather-based aggregation (one warp per dst node)
    int blocks = (n * 32 + 255) / 256;
    k_agg<<<blocks, 256>>>((float*)d_out, n);
}

// round 13
// speedup vs baseline: 1.6486x; 1.1491x over previous
#include <cuda_runtime.h>
#include <cuda_fp16.h>

#define NMAX 50000
#define EMAX 800000
#define D    128
#define EPSF 1e-6f

// ------------------------- device scratch (no mallocs allowed) -------------
// Interleaved fp16 feature rows: per node 256 halfs = [m0..m127 | v0..v127] (512B)
__device__ uint4 g_h4[NMAX * 32];      // 25.6 MB
__device__ int   g_count[NMAX];        // in-degree histogram
__device__ int   g_start[NMAX + 1];    // CSR row offsets (by dst)
__device__ int   g_cursor[NMAX];       // placement cursors
__device__ int   g_part[256];          // scan block partials

struct __align__(16) EData { int src; float w0; float w1; int pad; };
__device__ EData g_edata[EMAX];        // dst-sorted edge payload, 12.8 MB

// ------------------------- f32x2 helpers (FFMA2 path) ----------------------
__device__ __forceinline__ unsigned long long pack2(float lo, float hi) {
    unsigned long long r;
    asm("mov.b64 %0, {%1, %2};" : "=l"(r) : "f"(lo), "f"(hi));
    return r;
}
__device__ __forceinline__ void unpack2(unsigned long long v, float &lo, float &hi) {
    asm("mov.b64 {%0, %1}, %2;" : "=f"(lo), "=f"(hi) : "l"(v));
}
__device__ __forceinline__ void fma2(unsigned long long &acc,
                                     unsigned long long a,
                                     unsigned long long b) {
    asm("fma.rn.f32x2 %0, %1, %2, %0;" : "+l"(acc) : "l"(a), "l"(b));
}

// ------------------------- CSR build -------------------------------------
__global__ void k_zero_count(int n) {
    int i = blockIdx.x * blockDim.x + threadIdx.x;
    if (i < n) g_count[i] = 0;
}

__global__ void k_hist(const int* __restrict__ dst, int e) {
    int i = blockIdx.x * blockDim.x + threadIdx.x;
    if (i < e) atomicAdd(&g_count[dst[i]], 1);
}

// Scan phase A: per-block sums of g_count.
__global__ void k_scanA(int n) {
    __shared__ int s[256];
    int i = blockIdx.x * 256 + threadIdx.x;
    s[threadIdx.x] = (i < n) ? g_count[i] : 0;
    __syncthreads();
#pragma unroll
    for (int o = 128; o > 0; o >>= 1) {
        if (threadIdx.x < o) s[threadIdx.x] += s[threadIdx.x + o];
        __syncthreads();
    }
    if (threadIdx.x == 0) g_part[blockIdx.x] = s[0];
}

// Scan phase C (B fused): every block redundantly scans the <=256 partials in
// smem to get its offset, then does its local exclusive scan.
__global__ void k_scanC(int n, int nb) {
    __shared__ int sp[256];
    __shared__ int s[256];
    int t = threadIdx.x;
    sp[t] = (t < nb) ? g_part[t] : 0;
    int i = blockIdx.x * 256 + t;
    int c = (i < n) ? g_count[i] : 0;
    s[t] = c;
    __syncthreads();
#pragma unroll
    for (int o = 1; o < 256; o <<= 1) {
        int vp = (t >= o) ? sp[t - o] : 0;
        int vl = (t >= o) ? s[t - o] : 0;
        __syncthreads();
        sp[t] += vp;
        s[t]  += vl;
        __syncthreads();
    }
    int blockoff = (blockIdx.x == 0) ? 0 : sp[blockIdx.x - 1];
    int ex = s[t] - c + blockoff;
    if (i < n) {
        g_start[i]  = ex;
        g_cursor[i] = ex;
        if (i == n - 1) g_start[n] = ex + c;
    }
}

// Placement: scatter full 16B edge payload {src, w0, w1} into sorted slot.
__global__ void k_place(const int* __restrict__ dst, const int* __restrict__ esrc,
                        const float* __restrict__ w0, const float* __restrict__ w1,
                        int e) {
    int i = blockIdx.x * blockDim.x + threadIdx.x;
    if (i < e) {
        int p = atomicAdd(&g_cursor[dst[i]], 1);
        EData ed;
        ed.src = esrc[i];
        ed.w0  = w0[i];
        ed.w1  = w1[i];
        ed.pad = 0;
        *(uint4*)&g_edata[p] = *(uint4*)&ed;
    }
}

// ------------------------- dense phase ------------------------------------
// Block = 256 threads = 8 warps. Each warp computes 8 nodes x 128 features
// (halves W L1 traffic vs 4 nodes/warp). Two phases reuse one 32KB smem
// buffer: mean-GEMM, then var-GEMM; epilogue gates and stores fp16 rows.
__device__ __forceinline__ void gemm8(const float* __restrict__ sx,
                                      const float4* __restrict__ W4,
                                      int base, int lane,
                                      unsigned long long acc[8][2]) {
#pragma unroll 4
    for (int k = 0; k < D; k += 4) {
        float4 w0 = __ldg(&W4[(k + 0) * (D / 4) + lane]);
        float4 w1 = __ldg(&W4[(k + 1) * (D / 4) + lane]);
        float4 w2 = __ldg(&W4[(k + 2) * (D / 4) + lane]);
        float4 w3 = __ldg(&W4[(k + 3) * (D / 4) + lane]);
        unsigned long long w0a = pack2(w0.x, w0.y), w0b = pack2(w0.z, w0.w);
        unsigned long long w1a = pack2(w1.x, w1.y), w1b = pack2(w1.z, w1.w);
        unsigned long long w2a = pack2(w2.x, w2.y), w2b = pack2(w2.z, w2.w);
        unsigned long long w3a = pack2(w3.x, w3.y), w3b = pack2(w3.z, w3.w);
#pragma unroll
        for (int i = 0; i < 8; i++) {
            float4 a = *(const float4*)(sx + (base + i) * D + k);
            unsigned long long t;
            t = pack2(a.x, a.x); fma2(acc[i][0], w0a, t); fma2(acc[i][1], w0b, t);
            t = pack2(a.y, a.y); fma2(acc[i][0], w1a, t); fma2(acc[i][1], w1b, t);
            t = pack2(a.z, a.z); fma2(acc[i][0], w2a, t); fma2(acc[i][1], w2b, t);
            t = pack2(a.w, a.w); fma2(acc[i][0], w3a, t); fma2(acc[i][1], w3b, t);
        }
    }
}

__device__ __forceinline__ void load_rows(float* __restrict__ sx,
                                          const float* __restrict__ src,
                                          int nb, int n, int tid) {
    for (int i = tid; i < 64 * (D / 4); i += 256) {
        int nl   = i >> 5;
        int col4 = (i & 31) << 2;
        int node = nb + nl;
        float4 a = make_float4(0.f, 0.f, 0.f, 0.f);
        if (node < n) a = *(const float4*)(src + (long)node * D + col4);
        *(float4*)(sx + nl * D + col4) = a;
    }
}

__global__ void __launch_bounds__(256, 2)
k_dense(const float* __restrict__ mean, const float* __restrict__ var,
        const float* __restrict__ Wm,   const float* __restrict__ bm,
        const float* __restrict__ Wv,   const float* __restrict__ bv, int n) {
    __shared__ float sx[64 * D];   // 32 KB, reused across phases

    const int tid  = threadIdx.x;
    const int warp = tid >> 5;
    const int lane = tid & 31;
    const int nb   = blockIdx.x * 64;
    const int base = warp << 3;    // this warp's first local node

    unsigned long long accm[8][2], accv[8][2];
#pragma unroll
    for (int i = 0; i < 8; i++) {
        accm[i][0] = 0ull; accm[i][1] = 0ull;
        accv[i][0] = 0ull; accv[i][1] = 0ull;
    }

    // phase M
    load_rows(sx, mean, nb, n, tid);
    __syncthreads();
    gemm8(sx, (const float4*)Wm, base, lane, accm);
    __syncthreads();

    // phase V
    load_rows(sx, var, nb, n, tid);
    __syncthreads();
    gemm8(sx, (const float4*)Wv, base, lane, accv);

    // epilogue: +bias, ELU / ReLU+eps, attention gate, fp16 store
    float4 bm4 = __ldg((const float4*)bm + lane);
    float4 bv4 = __ldg((const float4*)bv + lane);

#pragma unroll
    for (int i = 0; i < 8; i++) {
        int node = nb + base + i;
        if (node >= n) continue;
        float m0, m1, m2, m3, v0, v1, v2, v3;
        unpack2(accm[i][0], m0, m1);
        unpack2(accm[i][1], m2, m3);
        unpack2(accv[i][0], v0, v1);
        unpack2(accv[i][1], v2, v3);
        m0 += bm4.x; m1 += bm4.y; m2 += bm4.z; m3 += bm4.w;
        v0 += bv4.x; v1 += bv4.y; v2 += bv4.z; v3 += bv4.w;
        m0 = (m0 > 0.f) ? m0 : expm1f(m0);
        m1 = (m1 > 0.f) ? m1 : expm1f(m1);
        m2 = (m2 > 0.f) ? m2 : expm1f(m2);
        m3 = (m3 > 0.f) ? m3 : expm1f(m3);
        v0 = fmaxf(v0, 0.f) + EPSF;
        v1 = fmaxf(v1, 0.f) + EPSF;
        v2 = fmaxf(v2, 0.f) + EPSF;
        v3 = fmaxf(v3, 0.f) + EPSF;
        float a0 = __expf(-v0), a1 = __expf(-v1), a2 = __expf(-v2), a3 = __expf(-v3);
        m0 *= a0; m1 *= a1; m2 *= a2; m3 *= a3;
        v0 *= a0 * a0; v1 *= a1 * a1; v2 *= a2 * a2; v3 *= a3 * a3;

        __half* row = (__half*)g_h4 + (long)node * 256;
        __half2 hm01 = __floats2half2_rn(m0, m1);
        __half2 hm23 = __floats2half2_rn(m2, m3);
        __half2 hv01 = __floats2half2_rn(v0, v1);
        __half2 hv23 = __floats2half2_rn(v2, v3);
        uint2 um, uv;
        um.x = reinterpret_cast<unsigned&>(hm01);
        um.y = reinterpret_cast<unsigned&>(hm23);
        uv.x = reinterpret_cast<unsigned&>(hv01);
        uv.y = reinterpret_cast<unsigned&>(hv23);
        *(uint2*)(row + 4 * lane)       = um;
        *(uint2*)(row + 128 + 4 * lane) = uv;
    }
}

// ------------------------- aggregation ------------------------------------
// One warp per dst node. Lanes 0-15 own m features (8 each), lanes 16-31 own
// v features. 1-deep software pipeline: next payload AND next feature gather
// issue before the current edge's accumulate consumes its data.
__global__ void __launch_bounds__(256)
k_agg(float* __restrict__ out, int n) {
    int gwarp = (blockIdx.x * blockDim.x + threadIdx.x) >> 5;
    int lane  = threadIdx.x & 31;
    if (gwarp >= n) return;

    int s = g_start[gwarp];
    int t = g_start[gwarp + 1];

    const bool isv = lane >= 16;
    const int  l16 = lane & 15;
    const int  fo  = l16 * 8 + (isv ? 128 : 0);   // half offset within row

    unsigned long long acc0 = 0ull, acc1 = 0ull, acc2 = 0ull, acc3 = 0ull;

    if (s < t) {
        const __half* feat = (const __half*)g_h4;
        EData ed = g_edata[s];
        uint4 hv = *(const uint4*)(feat + (long)ed.src * 256 + fo);
        for (int idx = s; idx < t; idx++) {
            EData edn = ed;
            uint4 hvn = hv;
            if (idx + 1 < t) {
                edn = g_edata[idx + 1];
                hvn = *(const uint4*)(feat + (long)edn.src * 256 + fo);
            }
            float w = isv ? ed.w1 : ed.w0;
            unsigned long long ww = pack2(w, w);
            __half2 h0 = reinterpret_cast<__half2&>(hv.x);
            __half2 h1 = reinterpret_cast<__half2&>(hv.y);
            __half2 h2 = reinterpret_cast<__half2&>(hv.z);
            __half2 h3 = reinterpret_cast<__half2&>(hv.w);
            float2 f0 = __half22float2(h0);
            float2 f1 = __half22float2(h1);
            float2 f2 = __half22float2(h2);
            float2 f3 = __half22float2(h3);
            fma2(acc0, pack2(f0.x, f0.y), ww);
            fma2(acc1, pack2(f1.x, f1.y), ww);
            fma2(acc2, pack2(f2.x, f2.y), ww);
            fma2(acc3, pack2(f3.x, f3.y), ww);
            ed = edn;
            hv = hvn;
        }
    }

    float r0, r1, r2, r3, r4, r5, r6, r7;
    unpack2(acc0, r0, r1);
    unpack2(acc1, r2, r3);
    unpack2(acc2, r4, r5);
    unpack2(acc3, r6, r7);

    long rowbase = isv ? ((long)n * D + (long)gwarp * D) : ((long)gwarp * D);
    float* o = out + rowbase + l16 * 8;
    *(float4*)(o)     = make_float4(r0, r1, r2, r3);
    *(float4*)(o + 4) = make_float4(r4, r5, r6, r7);
}

// ------------------------- launch -----------------------------------------
extern "C" void kernel_launch(void* const* d_in, const int* in_sizes, int n_in,
                              void* d_out, int out_size) {
    const float* mean = (const float*)d_in[0];
    const float* var  = (const float*)d_in[1];
    const float* Wm   = (const float*)d_in[2];
    const float* bm   = (const float*)d_in[3];
    const float* Wv   = (const float*)d_in[4];
    const float* bv   = (const float*)d_in[5];
    const float* a0   = (const float*)d_in[6];
    const float* a1   = (const float*)d_in[7];
    const int*   esrc = (const int*)d_in[8];
    const int*   edst = (const int*)d_in[9];

    int n = in_sizes[0] / D;   // 50000
    int e = in_sizes[6];       // 800000
    int nb = (n + 255) / 256;  // scan blocks (196 <= 256)

    // lazily-created side stream + events (resources only; work is identical
    // on every call)
    static cudaStream_t s2 = nullptr;
    static cudaEvent_t evFork = nullptr, evJoin = nullptr;
    if (!s2) {
        cudaStreamCreateWithFlags(&s2, cudaStreamNonBlocking);
        cudaEventCreateWithFlags(&evFork, cudaEventDisableTiming);
        cudaEventCreateWithFlags(&evJoin, cudaEventDisableTiming);
    }

    // fork: CSR build chain on s2, overlapped with k_dense on the main stream
    cudaEventRecord(evFork, 0);
    cudaStreamWaitEvent(s2, evFork, 0);

    k_zero_count<<<nb, 256, 0, s2>>>(n);
    k_hist<<<(e + 255) / 256, 256, 0, s2>>>(edst, e);
    k_scanA<<<nb, 256, 0, s2>>>(n);
    k_scanC<<<nb, 256, 0, s2>>>(n, nb);
    k_place<<<(e + 255) / 256, 256, 0, s2>>>(edst, esrc, a0, a1, e);
    cudaEventRecord(evJoin, s2);

    // dense projections + gating (fp32 FFMA2 compute, fp16 store)
    k_dense<<<(n + 63) / 64, 256>>>(mean, var, Wm, bm, Wv, bv, n);

    // join, then gather-based aggregation (one warp per dst node)
    cudaStreamWaitEvent(0, evJoin, 0);
    int blocks = (n * 32 + 255) / 256;
    k_agg<<<blocks, 256>>>((float*)d_out, n);
}

// round 14
// speedup vs baseline: 1.6584x; 1.0059x over previous
#include <cuda_runtime.h>
#include <cuda_fp16.h>

#define NMAX 50000
#define EMAX 800000
#define D    128
#define EPSF 1e-6f

// ------------------------- device scratch (no mallocs allowed) -------------
// Interleaved fp16 feature rows: per node 256 halfs = [m0..m127 | v0..v127] (512B)
__device__ uint4 g_h4[NMAX * 32];      // 25.6 MB
__device__ int   g_count[NMAX];        // in-degree histogram
__device__ int   g_start[NMAX + 1];    // CSR row offsets (by dst)
__device__ int   g_cursor[NMAX];       // placement cursors
__device__ int   g_part[256];          // scan block partials

struct __align__(16) EData { int src; float w0; float w1; int pad; };
__device__ EData g_edata[EMAX];        // dst-sorted edge payload, 12.8 MB

// ------------------------- f32x2 helpers (FFMA2 path) ----------------------
__device__ __forceinline__ unsigned long long pack2(float lo, float hi) {
    unsigned long long r;
    asm("mov.b64 %0, {%1, %2};" : "=l"(r) : "f"(lo), "f"(hi));
    return r;
}
__device__ __forceinline__ void unpack2(unsigned long long v, float &lo, float &hi) {
    asm("mov.b64 {%0, %1}, %2;" : "=f"(lo), "=f"(hi) : "l"(v));
}
__device__ __forceinline__ void fma2(unsigned long long &acc,
                                     unsigned long long a,
                                     unsigned long long b) {
    asm("fma.rn.f32x2 %0, %1, %2, %0;" : "+l"(acc) : "l"(a), "l"(b));
}

// ------------------------- CSR build -------------------------------------
__global__ void k_zero_count(int n) {
    int i = blockIdx.x * blockDim.x + threadIdx.x;
    if (i < n) g_count[i] = 0;
}

__global__ void k_hist(const int* __restrict__ dst, int e) {
    int i = blockIdx.x * blockDim.x + threadIdx.x;
    if (i < e) atomicAdd(&g_count[dst[i]], 1);
}

// Scan phase A: per-block sums of g_count.
__global__ void k_scanA(int n) {
    __shared__ int s[256];
    int i = blockIdx.x * 256 + threadIdx.x;
    s[threadIdx.x] = (i < n) ? g_count[i] : 0;
    __syncthreads();
#pragma unroll
    for (int o = 128; o > 0; o >>= 1) {
        if (threadIdx.x < o) s[threadIdx.x] += s[threadIdx.x + o];
        __syncthreads();
    }
    if (threadIdx.x == 0) g_part[blockIdx.x] = s[0];
}

// Scan phase C (B fused): every block redundantly scans the <=256 partials in
// smem to get its offset, then does its local exclusive scan.
__global__ void k_scanC(int n, int nb) {
    __shared__ int sp[256];
    __shared__ int s[256];
    int t = threadIdx.x;
    sp[t] = (t < nb) ? g_part[t] : 0;
    int i = blockIdx.x * 256 + t;
    int c = (i < n) ? g_count[i] : 0;
    s[t] = c;
    __syncthreads();
#pragma unroll
    for (int o = 1; o < 256; o <<= 1) {
        int vp = (t >= o) ? sp[t - o] : 0;
        int vl = (t >= o) ? s[t - o] : 0;
        __syncthreads();
        sp[t] += vp;
        s[t]  += vl;
        __syncthreads();
    }
    int blockoff = (blockIdx.x == 0) ? 0 : sp[blockIdx.x - 1];
    int ex = s[t] - c + blockoff;
    if (i < n) {
        g_start[i]  = ex;
        g_cursor[i] = ex;
        if (i == n - 1) g_start[n] = ex + c;
    }
}

// Placement: scatter full 16B edge payload {src, w0, w1} into sorted slot.
__global__ void k_place(const int* __restrict__ dst, const int* __restrict__ esrc,
                        const float* __restrict__ w0, const float* __restrict__ w1,
                        int e) {
    int i = blockIdx.x * blockDim.x + threadIdx.x;
    if (i < e) {
        int p = atomicAdd(&g_cursor[dst[i]], 1);
        EData ed;
        ed.src = esrc[i];
        ed.w0  = w0[i];
        ed.w1  = w1[i];
        ed.pad = 0;
        *(uint4*)&g_edata[p] = *(uint4*)&ed;
    }
}

// ------------------------- dense phase ------------------------------------
// Block = 256 threads = 8 warps. Each warp computes 8 nodes x 128 features
// (halves W L1 traffic vs 4 nodes/warp). Two phases reuse one 32KB smem
// buffer: mean-GEMM, then var-GEMM; epilogue gates and stores fp16 rows.
__device__ __forceinline__ void gemm8(const float* __restrict__ sx,
                                      const float4* __restrict__ W4,
                                      int base, int lane,
                                      unsigned long long acc[8][2]) {
#pragma unroll 4
    for (int k = 0; k < D; k += 4) {
        float4 w0 = __ldg(&W4[(k + 0) * (D / 4) + lane]);
        float4 w1 = __ldg(&W4[(k + 1) * (D / 4) + lane]);
        float4 w2 = __ldg(&W4[(k + 2) * (D / 4) + lane]);
        float4 w3 = __ldg(&W4[(k + 3) * (D / 4) + lane]);
        unsigned long long w0a = pack2(w0.x, w0.y), w0b = pack2(w0.z, w0.w);
        unsigned long long w1a = pack2(w1.x, w1.y), w1b = pack2(w1.z, w1.w);
        unsigned long long w2a = pack2(w2.x, w2.y), w2b = pack2(w2.z, w2.w);
        unsigned long long w3a = pack2(w3.x, w3.y), w3b = pack2(w3.z, w3.w);
#pragma unroll
        for (int i = 0; i < 8; i++) {
            float4 a = *(const float4*)(sx + (base + i) * D + k);
            unsigned long long t;
            t = pack2(a.x, a.x); fma2(acc[i][0], w0a, t); fma2(acc[i][1], w0b, t);
            t = pack2(a.y, a.y); fma2(acc[i][0], w1a, t); fma2(acc[i][1], w1b, t);
            t = pack2(a.z, a.z); fma2(acc[i][0], w2a, t); fma2(acc[i][1], w2b, t);
            t = pack2(a.w, a.w); fma2(acc[i][0], w3a, t); fma2(acc[i][1], w3b, t);
        }
    }
}

__device__ __forceinline__ void load_rows(float* __restrict__ sx,
                                          const float* __restrict__ src,
                                          int nb, int n, int tid) {
    for (int i = tid; i < 64 * (D / 4); i += 256) {
        int nl   = i >> 5;
        int col4 = (i & 31) << 2;
        int node = nb + nl;
        float4 a = make_float4(0.f, 0.f, 0.f, 0.f);
        if (node < n) a = *(const float4*)(src + (long)node * D + col4);
        *(float4*)(sx + nl * D + col4) = a;
    }
}

__global__ void __launch_bounds__(256, 2)
k_dense(const float* __restrict__ mean, const float* __restrict__ var,
        const float* __restrict__ Wm,   const float* __restrict__ bm,
        const float* __restrict__ Wv,   const float* __restrict__ bv, int n) {
    __shared__ float sx[64 * D];   // 32 KB, reused across phases

    const int tid  = threadIdx.x;
    const int warp = tid >> 5;
    const int lane = tid & 31;
    const int nb   = blockIdx.x * 64;
    const int base = warp << 3;    // this warp's first local node

    unsigned long long accm[8][2], accv[8][2];
#pragma unroll
    for (int i = 0; i < 8; i++) {
        accm[i][0] = 0ull; accm[i][1] = 0ull;
        accv[i][0] = 0ull; accv[i][1] = 0ull;
    }

    // phase M
    load_rows(sx, mean, nb, n, tid);
    __syncthreads();
    gemm8(sx, (const float4*)Wm, base, lane, accm);
    __syncthreads();

    // phase V
    load_rows(sx, var, nb, n, tid);
    __syncthreads();
    gemm8(sx, (const float4*)Wv, base, lane, accv);

    // epilogue: +bias, ELU / ReLU+eps, attention gate, fp16 store
    float4 bm4 = __ldg((const float4*)bm + lane);
    float4 bv4 = __ldg((const float4*)bv + lane);

#pragma unroll
    for (int i = 0; i < 8; i++) {
        int node = nb + base + i;
        if (node >= n) continue;
        float m0, m1, m2, m3, v0, v1, v2, v3;
        unpack2(accm[i][0], m0, m1);
        unpack2(accm[i][1], m2, m3);
        unpack2(accv[i][0], v0, v1);
        unpack2(accv[i][1], v2, v3);
        m0 += bm4.x; m1 += bm4.y; m2 += bm4.z; m3 += bm4.w;
        v0 += bv4.x; v1 += bv4.y; v2 += bv4.z; v3 += bv4.w;
        m0 = (m0 > 0.f) ? m0 : expm1f(m0);
        m1 = (m1 > 0.f) ? m1 : expm1f(m1);
        m2 = (m2 > 0.f) ? m2 : expm1f(m2);
        m3 = (m3 > 0.f) ? m3 : expm1f(m3);
        v0 = fmaxf(v0, 0.f) + EPSF;
        v1 = fmaxf(v1, 0.f) + EPSF;
        v2 = fmaxf(v2, 0.f) + EPSF;
        v3 = fmaxf(v3, 0.f) + EPSF;
        float a0 = __expf(-v0), a1 = __expf(-v1), a2 = __expf(-v2), a3 = __expf(-v3);
        m0 *= a0; m1 *= a1; m2 *= a2; m3 *= a3;
        v0 *= a0 * a0; v1 *= a1 * a1; v2 *= a2 * a2; v3 *= a3 * a3;

        __half* row = (__half*)g_h4 + (long)node * 256;
        __half2 hm01 = __floats2half2_rn(m0, m1);
        __half2 hm23 = __floats2half2_rn(m2, m3);
        __half2 hv01 = __floats2half2_rn(v0, v1);
        __half2 hv23 = __floats2half2_rn(v2, v3);
        uint2 um, uv;
        um.x = reinterpret_cast<unsigned&>(hm01);
        um.y = reinterpret_cast<unsigned&>(hm23);
        uv.x = reinterpret_cast<unsigned&>(hv01);
        uv.y = reinterpret_cast<unsigned&>(hv23);
        *(uint2*)(row + 4 * lane)       = um;
        *(uint2*)(row + 128 + 4 * lane) = uv;
    }
}

// ------------------------- aggregation ------------------------------------
// One warp per dst node. Lanes 0-15 own m features (8 each), lanes 16-31 own
// v features. 1-deep software pipeline: next payload AND next feature gather
// issue before the current edge's accumulate consumes its data.
__global__ void __launch_bounds__(256)
k_agg(float* __restrict__ out, int n) {
    int gwarp = (blockIdx.x * blockDim.x + threadIdx.x) >> 5;
    int lane  = threadIdx.x & 31;
    if (gwarp >= n) return;

    int s = g_start[gwarp];
    int t = g_start[gwarp + 1];

    const bool isv = lane >= 16;
    const int  l16 = lane & 15;
    const int  fo  = l16 * 8 + (isv ? 128 : 0);   // half offset within row

    unsigned long long acc0 = 0ull, acc1 = 0ull, acc2 = 0ull, acc3 = 0ull;

    if (s < t) {
        const __half* feat = (const __half*)g_h4;
        EData ed = g_edata[s];
        uint4 hv = *(const uint4*)(feat + (long)ed.src * 256 + fo);
        for (int idx = s; idx < t; idx++) {
            EData edn = ed;
            uint4 hvn = hv;
            if (idx + 1 < t) {
                edn = g_edata[idx + 1];
                hvn = *(const uint4*)(feat + (long)edn.src * 256 + fo);
            }
            float w = isv ? ed.w1 : ed.w0;
            unsigned long long ww = pack2(w, w);
            __half2 h0 = reinterpret_cast<__half2&>(hv.x);
            __half2 h1 = reinterpret_cast<__half2&>(hv.y);
            __half2 h2 = reinterpret_cast<__half2&>(hv.z);
            __half2 h3 = reinterpret_cast<__half2&>(hv.w);
            float2 f0 = __half22float2(h0);
            float2 f1 = __half22float2(h1);
            float2 f2 = __half22float2(h2);
            float2 f3 = __half22float2(h3);
            fma2(acc0, pack2(f0.x, f0.y), ww);
            fma2(acc1, pack2(f1.x, f1.y), ww);
            fma2(acc2, pack2(f2.x, f2.y), ww);
            fma2(acc3, pack2(f3.x, f3.y), ww);
            ed = edn;
            hv = hvn;
        }
    }

    float r0, r1, r2, r3, r4, r5, r6, r7;
    unpack2(acc0, r0, r1);
    unpack2(acc1, r2, r3);
    unpack2(acc2, r4, r5);
    unpack2(acc3, r6, r7);

    long rowbase = isv ? ((long)n * D + (long)gwarp * D) : ((long)gwarp * D);
    float* o = out + rowbase + l16 * 8;
    *(float4*)(o)     = make_float4(r0, r1, r2, r3);
    *(float4*)(o + 4) = make_float4(r4, r5, r6, r7);
}

// ------------------------- launch -----------------------------------------
extern "C" void kernel_launch(void* const* d_in, const int* in_sizes, int n_in,
                              void* d_out, int out_size) {
    const float* mean = (const float*)d_in[0];
    const float* var  = (const float*)d_in[1];
    const float* Wm   = (const float*)d_in[2];
    const float* bm   = (const float*)d_in[3];
    const float* Wv   = (const float*)d_in[4];
    const float* bv   = (const float*)d_in[5];
    const float* a0   = (const float*)d_in[6];
    const float* a1   = (const float*)d_in[7];
    const int*   esrc = (const int*)d_in[8];
    const int*   edst = (const int*)d_in[9];

    int n = in_sizes[0] / D;   // 50000
    int e = in_sizes[6];       // 800000
    int nb = (n + 255) / 256;  // scan blocks (196 <= 256)

    // lazily-created side stream + events (resources only; work is identical
    // on every call)
    static cudaStream_t s2 = nullptr;
    static cudaEvent_t evFork = nullptr, evJoin = nullptr;
    if (!s2) {
        cudaStreamCreateWithFlags(&s2, cudaStreamNonBlocking);
        cudaEventCreateWithFlags(&evFork, cudaEventDisableTiming);
        cudaEventCreateWithFlags(&evJoin, cudaEventDisableTiming);
    }

    // fork: CSR build chain on s2, overlapped with k_dense on the main stream
    cudaEventRecord(evFork, 0);
    cudaStreamWaitEvent(s2, evFork, 0);

    k_zero_count<<<nb, 256, 0, s2>>>(n);
    k_hist<<<(e + 255) / 256, 256, 0, s2>>>(edst, e);
    k_scanA<<<nb, 256, 0, s2>>>(n);
    k_scanC<<<nb, 256, 0, s2>>>(n, nb);
    k_place<<<(e + 255) / 256, 256, 0, s2>>>(edst, esrc, a0, a1, e);
    cudaEventRecord(evJoin, s2);

    // dense projections + gating (fp32 FFMA2 compute, fp16 store)
    k_dense<<<(n + 63) / 64, 256>>>(mean, var, Wm, bm, Wv, bv, n);

    // join, then gather-based aggregation (one warp per dst node)
    cudaStreamWaitEvent(0, evJoin, 0);
    int blocks = (n * 32 + 255) / 256;
    k_agg<<<blocks, 256>>>((float*)d_out, n);
}